// round 7
// baseline (speedup 1.0000x reference)
#include <cuda_runtime.h>
#include <cuda_bf16.h>
#include <cstdint>
#include <math.h>

#define NDIM 512
#define C 128
#define NN (NDIM*NDIM)
#define PLANE NN
#define WSZ 17408          // bf16 elems per 128x136 array
#define WSZB 34816         // bytes

// ---------------------------------------------------------------------------
// scratch
// ---------------------------------------------------------------------------
__device__ __align__(16) float g_i[(size_t)C*NN];     // tf32-rounded, channel-major [c][i*512+k]
__device__ __align__(16) float g_j[(size_t)C*NN];
__device__ __align__(16) float g_ecm[(size_t)C*NN];   // einsum out
__device__ __align__(16) float g_sg [(size_t)NN*C];   // sigmoid(x@Ws+bs), row-major
// pre-split bf16 weights: [m][hi/lo][n][k], m: 0=Wis 1=Wi 2=Wjs 3=Wj 4=Ws 5=Wp
__device__ __align__(16) __nv_bfloat16 g_wq[6 * 2 * 128 * 128];

extern __shared__ char smem_[];

// ---------------------------------------------------------------------------
// PTX helpers (compute_103-portable)
// ---------------------------------------------------------------------------
__device__ __forceinline__ uint32_t smem_u32(const void* p) {
    uint32_t a;
    asm("{ .reg .u64 t; cvta.to.shared.u64 t, %1; cvt.u32.u64 %0, t; }" : "=r"(a) : "l"(p));
    return a;
}
__device__ __forceinline__ void ldm_x4(uint32_t addr, uint32_t* r) {
    asm volatile("ldmatrix.sync.aligned.m8n8.x4.shared.b16 {%0,%1,%2,%3}, [%4];"
        : "=r"(r[0]), "=r"(r[1]), "=r"(r[2]), "=r"(r[3]) : "r"(addr));
}
__device__ __forceinline__ void mma_bf16(float* d, const uint32_t* a, uint32_t b0, uint32_t b1) {
    asm volatile("mma.sync.aligned.m16n8k16.row.col.f32.bf16.bf16.f32 "
        "{%0,%1,%2,%3}, {%4,%5,%6,%7}, {%8,%9}, {%0,%1,%2,%3};"
        : "+f"(d[0]), "+f"(d[1]), "+f"(d[2]), "+f"(d[3])
        : "r"(a[0]), "r"(a[1]), "r"(a[2]), "r"(a[3]), "r"(b0), "r"(b1));
}
__device__ __forceinline__ void mma_tf32(float* d, const uint32_t* a, uint32_t b0, uint32_t b1) {
    asm volatile("mma.sync.aligned.m16n8k8.row.col.f32.tf32.tf32.f32 "
        "{%0,%1,%2,%3}, {%4,%5,%6,%7}, {%8,%9}, {%0,%1,%2,%3};"
        : "+f"(d[0]), "+f"(d[1]), "+f"(d[2]), "+f"(d[3])
        : "r"(a[0]), "r"(a[1]), "r"(a[2]), "r"(a[3]), "r"(b0), "r"(b1));
}
__device__ __forceinline__ void cp16(uint32_t dst, const void* src) {
    asm volatile("cp.async.cg.shared.global [%0], [%1], 16;" :: "r"(dst), "l"(src) : "memory");
}
#define CP_COMMIT() asm volatile("cp.async.commit_group;" ::: "memory")
#define CP_WAIT(n)  asm volatile("cp.async.wait_group %0;" :: "n"(n) : "memory")
__device__ __forceinline__ float sigmoidf_(float x) { return 1.0f / (1.0f + __expf(-x)); }
__device__ __forceinline__ void split_bf16(float v, __nv_bfloat16& h, __nv_bfloat16& l) {
    h = __float2bfloat16_rn(v);
    l = __float2bfloat16_rn(v - __bfloat162float(h));
}
__device__ __forceinline__ float tf32r(float x) {
    float r;
    asm("cvt.rna.tf32.f32 %0, %1;" : "=f"(r) : "f"(x));
    return r;
}

// ---------------------------------------------------------------------------
// Prologue: split+transpose 6 weights (bf16 hi/lo, [n][k])
// ---------------------------------------------------------------------------
__global__ void convert_w_kernel(const float* __restrict__ Wis, const float* __restrict__ Wi,
                                 const float* __restrict__ Wjs, const float* __restrict__ Wj,
                                 const float* __restrict__ Ws,  const float* __restrict__ Wp) {
    const float* src[6] = {Wis, Wi, Wjs, Wj, Ws, Wp};
    const float* W = src[blockIdx.x];
    __nv_bfloat16* outh = g_wq + (size_t)blockIdx.x * 32768;
    __nv_bfloat16* outl = outh + 16384;
    for (int idx = threadIdx.x; idx < 16384; idx += blockDim.x) {
        int n = idx >> 7, k = idx & 127;
        float v = W[k * 128 + n];
        __nv_bfloat16 h, l;
        split_bf16(v, h, l);
        outh[n * 128 + k] = h;
        outl[n * 128 + k] = l;
    }
}

// cp.async weight pair (hi at sW, lo at sW+WSZB)
__device__ __forceinline__ void loadWq512(int m, uint32_t sW, int tid) {
    const char* src = (const char*)g_wq + (size_t)m * 65536;
    #pragma unroll
    for (int it = 0; it < 8; ++it) {
        int idx = tid + it * 512;
        int arr = idx >> 11, rem = idx & 2047;
        int row = rem >> 4, ch = rem & 15;
        cp16(sW + arr * WSZB + row * 272 + ch * 16,
             src + arr * 32768 + row * 256 + ch * 16);
    }
}

// ---------------------------------------------------------------------------
// bf16 3-term warp GEMM (32x32 warp tile, K=128, row stride 272 B)
// ---------------------------------------------------------------------------
__device__ __forceinline__ void wgemm16(uint32_t sA, uint32_t aLo,
                                        uint32_t sB, uint32_t bLo,
                                        int lane, int wm, int wn, float* acc) {
    int lr = lane & 7, sel = lane >> 3;
    uint32_t aRow = (uint32_t)((wm*32 + (sel & 1)*8 + lr) * 272 + (sel >> 1)*16);
    uint32_t bRow = (uint32_t)((wn*32 + (sel >> 1)*8 + lr) * 272 + (sel & 1)*16);
    #pragma unroll
    for (int kk = 0; kk < 8; ++kk) {
        uint32_t ah[2][4], al[2][4];
        #pragma unroll
        for (int ma = 0; ma < 2; ++ma) {
            uint32_t off = aRow + (uint32_t)(ma * 16 * 272 + kk * 32);
            ldm_x4(sA + off, ah[ma]);
            ldm_x4(sA + aLo + off, al[ma]);
        }
        #pragma unroll
        for (int p = 0; p < 2; ++p) {
            uint32_t bh[4], bl[4];
            uint32_t off = bRow + (uint32_t)(p * 16 * 272 + kk * 32);
            ldm_x4(sB + off, bh);
            ldm_x4(sB + bLo + off, bl);
            #pragma unroll
            for (int ma = 0; ma < 2; ++ma)
                #pragma unroll
                for (int h = 0; h < 2; ++h) {
                    float* d = acc + (ma*4 + p*2 + h)*4;
                    int s = h * 2;
                    mma_bf16(d, ah[ma], bh[s], bh[s+1]);
                    mma_bf16(d, ah[ma], bl[s], bl[s+1]);
                    mma_bf16(d, al[ma], bh[s], bh[s+1]);
                }
        }
    }
}

// dual-output variant: shared A fragments, two B matrices (gate W0, main W1)
__device__ __forceinline__ void wgemm_dual(uint32_t sA, uint32_t sW0, uint32_t sW1,
                                           int lane, int wm, int wn,
                                           float* accg, float* accm) {
    int lr = lane & 7, sel = lane >> 3;
    uint32_t aRow = (uint32_t)((wm*32 + (sel & 1)*8 + lr) * 272 + (sel >> 1)*16);
    uint32_t bRow = (uint32_t)((wn*32 + (sel >> 1)*8 + lr) * 272 + (sel & 1)*16);
    #pragma unroll
    for (int kk = 0; kk < 8; ++kk) {
        uint32_t ah[2][4], al[2][4];
        #pragma unroll
        for (int ma = 0; ma < 2; ++ma) {
            uint32_t off = aRow + (uint32_t)(ma * 16 * 272 + kk * 32);
            ldm_x4(sA + off, ah[ma]);
            ldm_x4(sA + WSZB + off, al[ma]);
        }
        #pragma unroll
        for (int p = 0; p < 2; ++p) {
            uint32_t off = bRow + (uint32_t)(p * 16 * 272 + kk * 32);
            uint32_t bh[4], bl[4];
            ldm_x4(sW0 + off, bh);
            ldm_x4(sW0 + WSZB + off, bl);
            #pragma unroll
            for (int ma = 0; ma < 2; ++ma)
                #pragma unroll
                for (int h = 0; h < 2; ++h) {
                    float* d = accg + (ma*4 + p*2 + h)*4;
                    int s = h * 2;
                    mma_bf16(d, ah[ma], bh[s], bh[s+1]);
                    mma_bf16(d, ah[ma], bl[s], bl[s+1]);
                    mma_bf16(d, al[ma], bh[s], bh[s+1]);
                }
            ldm_x4(sW1 + off, bh);
            ldm_x4(sW1 + WSZB + off, bl);
            #pragma unroll
            for (int ma = 0; ma < 2; ++ma)
                #pragma unroll
                for (int h = 0; h < 2; ++h) {
                    float* d = accm + (ma*4 + p*2 + h)*4;
                    int s = h * 2;
                    mma_bf16(d, ah[ma], bh[s], bh[s+1]);
                    mma_bf16(d, ah[ma], bl[s], bl[s+1]);
                    mma_bf16(d, al[ma], bh[s], bh[s+1]);
                }
        }
    }
}

// ---------------------------------------------------------------------------
// Stage 1: LN(x) + 5 GEMMs (dual-fused), 512 threads, smem 208896 B
// i/j outputs: single fp32 (tf32-rounded) channel-major planes
// ---------------------------------------------------------------------------
__global__ void __launch_bounds__(512, 1)
stage1_kernel(const float* __restrict__ x2d, const float* __restrict__ mask,
              const float* __restrict__ ga1, const float* __restrict__ be1,
              const float* __restrict__ bi,  const float* __restrict__ bis,
              const float* __restrict__ bj,  const float* __restrict__ bjs,
              const float* __restrict__ bs) {
    __nv_bfloat16* Xh = (__nv_bfloat16*)smem_;
    float* T1f = (float*)(smem_ + 4 * WSZB);   // W1 region doubles as f32 staging
    uint32_t sX  = smem_u32(Xh);
    uint32_t sW0 = sX + 2 * WSZB;
    uint32_t sW1 = sX + 4 * WSZB;

    int tid = threadIdx.x, lane = tid & 31, w = tid >> 5;
    int wm = w >> 2, wn = w & 3;
    int g = lane >> 2, t2 = (lane & 3) * 2;
    size_t rowbase = (size_t)blockIdx.x * 128;

    loadWq512(0, sW0, tid); CP_COMMIT();   // Wis
    loadWq512(1, sW1, tid); CP_COMMIT();   // Wi

    // layernorm: 4 threads/row, 32 channels each
    {
        int r = tid >> 2, e = tid & 3;
        const float* xr = x2d + (rowbase + r) * C + e * 32;
        float v[32], s = 0.f, ss = 0.f;
        #pragma unroll
        for (int t = 0; t < 8; ++t) {
            float4 f = *(const float4*)(xr + t * 4);
            v[4*t+0]=f.x; v[4*t+1]=f.y; v[4*t+2]=f.z; v[4*t+3]=f.w;
            s += f.x + f.y + f.z + f.w;
            ss += f.x*f.x + f.y*f.y + f.z*f.z + f.w*f.w;
        }
        s  += __shfl_xor_sync(0xffffffffu, s, 1);
        s  += __shfl_xor_sync(0xffffffffu, s, 2);
        ss += __shfl_xor_sync(0xffffffffu, ss, 1);
        ss += __shfl_xor_sync(0xffffffffu, ss, 2);
        float mu = s * (1.0f / C);
        float rs = rsqrtf(ss * (1.0f / C) - mu * mu + 1e-5f);
        #pragma unroll
        for (int t = 0; t < 32; ++t) {
            int k = e * 32 + t;
            float xn = (v[t] - mu) * rs * __ldg(ga1 + k) + __ldg(be1 + k);
            __nv_bfloat16 h, l;
            split_bf16(xn, h, l);
            Xh[r * 136 + k] = h;
            Xh[WSZ + r * 136 + k] = l;
        }
    }

    float accg[32], accm[32];

    #pragma unroll 1
    for (int pass = 0; pass < 2; ++pass) {
        const float* bgp = pass ? bjs : bis;
        const float* bmp = pass ? bj  : bi;
        float* outp = pass ? g_j : g_i;

        CP_WAIT(0);
        __syncthreads();
        #pragma unroll
        for (int q = 0; q < 32; ++q) { accg[q] = 0.f; accm[q] = 0.f; }
        wgemm_dual(sX, sW0, sW1, lane, wm, wn, accg, accm);
        __syncthreads();                       // done reading W0/W1
        loadWq512(pass ? 4 : 2, sW0, tid);     // prefetch next gate / Ws
        CP_COMMIT();

        // combine -> staging T1f[col][row] (tf32-rounded f32)
        #pragma unroll
        for (int ma = 0; ma < 2; ++ma) {
            int r0 = wm*32 + ma*16 + g;
            float m0 = __ldg(mask + rowbase + r0);
            float m1 = __ldg(mask + rowbase + r0 + 8);
            #pragma unroll
            for (int na = 0; na < 4; ++na) {
                int idx = (ma*4 + na) * 4;
                int c0 = wn*32 + na*8 + t2;
                float bg0 = __ldg(bgp + c0), bg1 = __ldg(bgp + c0 + 1);
                float b0 = __ldg(bmp + c0),  b1 = __ldg(bmp + c0 + 1);
                T1f[(c0  )*132 + r0    ] = tf32r((accm[idx+0] + b0) * sigmoidf_(accg[idx+0] + bg0) * m0);
                T1f[(c0+1)*132 + r0    ] = tf32r((accm[idx+1] + b1) * sigmoidf_(accg[idx+1] + bg1) * m0);
                T1f[(c0  )*132 + r0 + 8] = tf32r((accm[idx+2] + b0) * sigmoidf_(accg[idx+2] + bg0) * m1);
                T1f[(c0+1)*132 + r0 + 8] = tf32r((accm[idx+3] + b1) * sigmoidf_(accg[idx+3] + bg1) * m1);
            }
        }
        __syncthreads();

        // channel-major flush (f32)
        {
            int cch = tid >> 2, q = tid & 3;
            const float4* src = (const float4*)(T1f + cch * 132 + q * 32);
            float4* dst = (float4*)(outp + (size_t)cch * PLANE + rowbase + q * 32);
            #pragma unroll
            for (int t = 0; t < 8; ++t) dst[t] = src[t];
        }
        __syncthreads();
        if (pass == 0) { loadWq512(3, sW1, tid); CP_COMMIT(); }   // Wj
    }

    // sg = sigmoid(x@Ws+bs)
    CP_WAIT(0);
    __syncthreads();
    #pragma unroll
    for (int q = 0; q < 32; ++q) accg[q] = 0.f;
    wgemm16(sX, WSZB, sW0, WSZB, lane, wm, wn, accg);
    #pragma unroll
    for (int ma = 0; ma < 2; ++ma) {
        size_t r0 = rowbase + wm*32 + ma*16 + g;
        #pragma unroll
        for (int na = 0; na < 4; ++na) {
            int idx = (ma*4 + na) * 4;
            int c0 = wn*32 + na*8 + t2;
            float b0 = __ldg(bs + c0), b1 = __ldg(bs + c0 + 1);
            *(float2*)(g_sg + r0 * C + c0) =
                make_float2(sigmoidf_(accg[idx+0] + b0), sigmoidf_(accg[idx+1] + b1));
            *(float2*)(g_sg + (r0 + 8) * C + c0) =
                make_float2(sigmoidf_(accg[idx+2] + b0), sigmoidf_(accg[idx+3] + b1));
        }
    }
}

// ---------------------------------------------------------------------------
// Stage 2: einsum, tf32 single-pass. block 128x256, 512 threads, 3 stages.
// stage: A 128 rows x 36 f32 (144 B) = 18432, B 256 x 144 B = 36864 -> 55296 B
// ---------------------------------------------------------------------------
#define ESTG 55296

__device__ __forceinline__ void e_load(uint32_t sdst,
                                       const char* pA, const char* pB,
                                       int kb, int tid) {
    // A: iterations 0-1 (1024 chunks), B: iterations 2-5 (2048 chunks)
    #pragma unroll
    for (int it = 0; it < 2; ++it) {
        int idx = tid + it * 512;
        int row = idx >> 3, ch = idx & 7;
        cp16(sdst + row * 144 + ch * 16,
             pA + (size_t)row * 2048 + kb * 128 + ch * 16);
    }
    #pragma unroll
    for (int it = 0; it < 4; ++it) {
        int idx = tid + it * 512;
        int row = idx >> 3, ch = idx & 7;
        cp16(sdst + 18432 + row * 144 + ch * 16,
             pB + (size_t)row * 2048 + kb * 128 + ch * 16);
    }
}

__device__ __forceinline__ void e_mma(uint32_t st, int lane, int wm, int wn, float* acc) {
    int lr = lane & 7, sel = lane >> 3;
    uint32_t aRow = (uint32_t)((wm*32 + (sel & 1)*8 + lr) * 144 + (sel >> 1)*16);
    uint32_t bRow = (uint32_t)((wn*64 + (sel & 1)*8 + lr) * 144 + (sel >> 1)*16);
    uint32_t sA = st, sB = st + 18432;
    #pragma unroll
    for (int kk = 0; kk < 4; ++kk) {           // 4 x k8 = k32 chunk
        uint32_t a[2][4];
        #pragma unroll
        for (int ma = 0; ma < 2; ++ma)
            ldm_x4(sA + aRow + (uint32_t)(ma * 16 * 144 + kk * 32), a[ma]);
        #pragma unroll
        for (int p = 0; p < 4; ++p) {
            uint32_t b[4];
            ldm_x4(sB + bRow + (uint32_t)(p * 16 * 144 + kk * 32), b);
            #pragma unroll
            for (int ma = 0; ma < 2; ++ma) {
                mma_tf32(acc + (ma*8 + p*2 + 0)*4, a[ma], b[0], b[2]);
                mma_tf32(acc + (ma*8 + p*2 + 1)*4, a[ma], b[1], b[3]);
            }
        }
    }
}

__global__ void __launch_bounds__(512, 1)
einsum_kernel() {
    uint32_t sb = smem_u32(smem_);
    int tid = threadIdx.x, lane = tid & 31, w = tid >> 5;
    int wm = w >> 2, wn = w & 3;
    int g = lane >> 2, t2 = (lane & 3) * 2;
    int c = blockIdx.z;
    int ibase = blockIdx.x * 128, jbase = blockIdx.y * 256;

    const char* pA = (const char*)(g_i + (size_t)c * PLANE + (size_t)ibase * NDIM);
    const char* pB = (const char*)(g_j + (size_t)c * PLANE + (size_t)jbase * NDIM);

    float acc[64];
    #pragma unroll
    for (int q = 0; q < 64; ++q) acc[q] = 0.f;

    e_load(sb,        pA, pB, 0, tid); CP_COMMIT();
    e_load(sb + ESTG, pA, pB, 1, tid); CP_COMMIT();

    #pragma unroll 1
    for (int kb = 0; kb < 16; ++kb) {
        if (kb < 15) { CP_WAIT(1); } else { CP_WAIT(0); }
        __syncthreads();
        if (kb + 2 < 16) {
            e_load(sb + ((kb + 2) % 3) * ESTG, pA, pB, kb + 2, tid);
            CP_COMMIT();
        }
        e_mma(sb + (kb % 3) * ESTG, lane, wm, wn, acc);
        __syncthreads();
    }

    float* O = g_ecm + (size_t)c * PLANE;
    #pragma unroll
    for (int ma = 0; ma < 2; ++ma) {
        size_t r0 = (size_t)(ibase + wm*32 + ma*16 + g);
        #pragma unroll
        for (int na = 0; na < 8; ++na) {
            int idx = (ma*8 + na) * 4;
            int c0 = jbase + wn*64 + na*8 + t2;
            *(float2*)(O + r0 * NDIM + c0)       = make_float2(acc[idx+0], acc[idx+1]);
            *(float2*)(O + (r0 + 8) * NDIM + c0) = make_float2(acc[idx+2], acc[idx+3]);
        }
    }
}

// ---------------------------------------------------------------------------
// Stage 3: 128-row blocks, 512 threads. Coalesced gather -> smem Xf[c][r]
// (stride 133 f32, conflict-free), warp-per-row LN, bf16 3-term GEMM.
// smem: Xf 68096 | Xh/Xl 69632 | W 69632 = 207360 B
// ---------------------------------------------------------------------------
__global__ void __launch_bounds__(512, 1)
stage3_kernel(const float* __restrict__ mask,
              const float* __restrict__ ga2, const float* __restrict__ be2,
              const float* __restrict__ bp,  float* __restrict__ out) {
    float* Xf = (float*)smem_;                       // [128 c][133]
    __nv_bfloat16* Xh = (__nv_bfloat16*)(smem_ + 68096);
    uint32_t sX = smem_u32(Xh);
    uint32_t sW = sX + 2 * WSZB;

    int tid = threadIdx.x, lane = tid & 31, w = tid >> 5;
    int wm = w >> 2, wn = w & 3;
    int g = lane >> 2, t2 = (lane & 3) * 2;
    size_t rowbase = (size_t)blockIdx.x * 128;

    loadWq512(5, sW, tid);
    CP_COMMIT();

    // coalesced gather: g_ecm[c][rowbase + r] -> Xf[c][r]
    #pragma unroll
    for (int it = 0; it < 32; ++it) {
        int idx = tid + it * 512;
        int c = idx >> 7, r = idx & 127;
        Xf[c * 133 + r] = __ldg(g_ecm + (size_t)c * PLANE + rowbase + r);
    }
    __syncthreads();

    // LN: warp per row, lane owns channels {lane, lane+32, lane+64, lane+96}
    #pragma unroll 1
    for (int it = 0; it < 8; ++it) {
        int r = w + it * 16;
        float v[4], s = 0.f, ss = 0.f;
        #pragma unroll
        for (int q = 0; q < 4; ++q) {
            float x = Xf[(lane + 32*q) * 133 + r];
            v[q] = x; s += x; ss += x * x;
        }
        #pragma unroll
        for (int d = 16; d >= 1; d >>= 1) {
            s  += __shfl_xor_sync(0xffffffffu, s, d);
            ss += __shfl_xor_sync(0xffffffffu, ss, d);
        }
        float mu = s * (1.0f / C);
        float rs = rsqrtf(ss * (1.0f / C) - mu * mu + 1e-5f);
        #pragma unroll
        for (int q = 0; q < 4; ++q) {
            int k = lane + 32*q;
            float xn = (v[q] - mu) * rs * __ldg(ga2 + k) + __ldg(be2 + k);
            __nv_bfloat16 h, l;
            split_bf16(xn, h, l);
            Xh[r * 136 + k] = h;
            Xh[WSZ + r * 136 + k] = l;
        }
    }
    CP_WAIT(0);
    __syncthreads();

    float acc[32];
    #pragma unroll
    for (int q = 0; q < 32; ++q) acc[q] = 0.f;
    wgemm16(sX, WSZB, sW, WSZB, lane, wm, wn, acc);

    #pragma unroll
    for (int ma = 0; ma < 2; ++ma) {
        size_t r0 = rowbase + wm*32 + ma*16 + g;
        float m0 = __ldg(mask + r0);
        float m1 = __ldg(mask + r0 + 8);
        #pragma unroll
        for (int na = 0; na < 4; ++na) {
            int idx = (ma*4 + na) * 4;
            int c0 = wn*32 + na*8 + t2;
            float b0 = __ldg(bp + c0), b1 = __ldg(bp + c0 + 1);
            float2 s0 = *(const float2*)(g_sg + r0 * C + c0);
            float2 s1 = *(const float2*)(g_sg + (r0 + 8) * C + c0);
            *(float2*)(out + r0 * C + c0) =
                make_float2((acc[idx+0] + b0) * s0.x * m0, (acc[idx+1] + b1) * s0.y * m0);
            *(float2*)(out + (r0 + 8) * C + c0) =
                make_float2((acc[idx+2] + b0) * s1.x * m1, (acc[idx+3] + b1) * s1.y * m1);
        }
    }
}

// ---------------------------------------------------------------------------
extern "C" void kernel_launch(void* const* d_in, const int* in_sizes, int n_in,
                              void* d_out, int out_size) {
    const float* x2d  = (const float*)d_in[0];
    const float* mask = (const float*)d_in[1];
    const float* ga1  = (const float*)d_in[2];
    const float* be1  = (const float*)d_in[3];
    const float* ga2  = (const float*)d_in[4];
    const float* be2  = (const float*)d_in[5];
    const float* Wi   = (const float*)d_in[6];
    const float* bi   = (const float*)d_in[7];
    const float* Wis  = (const float*)d_in[8];
    const float* bis  = (const float*)d_in[9];
    const float* Wj   = (const float*)d_in[10];
    const float* bj   = (const float*)d_in[11];
    const float* Wjs  = (const float*)d_in[12];
    const float* bjs  = (const float*)d_in[13];
    const float* Wp   = (const float*)d_in[14];
    const float* bp   = (const float*)d_in[15];
    const float* Ws   = (const float*)d_in[16];
    const float* bs   = (const float*)d_in[17];

    const int smem_s1 = 6 * WSZB;            // 208896
    const int smem_e  = 3 * ESTG;            // 165888
    const int smem_s3 = 68096 + 4 * WSZB;    // 207360
    cudaFuncSetAttribute(stage1_kernel, cudaFuncAttributeMaxDynamicSharedMemorySize, smem_s1);
    cudaFuncSetAttribute(einsum_kernel, cudaFuncAttributeMaxDynamicSharedMemorySize, smem_e);
    cudaFuncSetAttribute(stage3_kernel, cudaFuncAttributeMaxDynamicSharedMemorySize, smem_s3);

    convert_w_kernel<<<6, 256>>>(Wis, Wi, Wjs, Wj, Ws, Wp);

    stage1_kernel<<<NN / 128, 512, smem_s1>>>(x2d, mask, ga1, be1,
                                              bi, bis, bj, bjs, bs);

    dim3 grid2(NDIM / 128, NDIM / 256, C);
    einsum_kernel<<<grid2, 512, smem_e>>>();

    stage3_kernel<<<NN / 128, 512, smem_s3>>>(mask, ga2, be2, bp, (float*)d_out);
}

// round 9
// speedup vs baseline: 1.0816x; 1.0816x over previous
#include <cuda_runtime.h>
#include <cuda_bf16.h>
#include <cstdint>
#include <math.h>

#define NDIM 512
#define C 128
#define NN (NDIM*NDIM)
#define PLANE NN
#define WFB 67584          // bytes per smem 128x132 f32 array

// ---------------------------------------------------------------------------
// scratch
// ---------------------------------------------------------------------------
__device__ __align__(16) float g_i[(size_t)C*NN];     // tf32-rounded, channel-major [c][i*512+k]
__device__ __align__(16) float g_j[(size_t)C*NN];
__device__ __align__(16) float g_ecm[(size_t)C*NN];   // einsum out
__device__ __align__(16) float g_sg [(size_t)NN*C];   // sigmoid(x@Ws+bs), row-major
// tf32-rounded transposed weights [m][n][k], m: 0=Wis 1=Wi 2=Wjs 3=Wj 4=Ws 5=Wp
__device__ __align__(16) float g_wf[6 * 128 * 128];

extern __shared__ char smem_[];

// ---------------------------------------------------------------------------
// PTX helpers (compute_103-portable)
// ---------------------------------------------------------------------------
__device__ __forceinline__ uint32_t smem_u32(const void* p) {
    uint32_t a;
    asm("{ .reg .u64 t; cvta.to.shared.u64 t, %1; cvt.u32.u64 %0, t; }" : "=r"(a) : "l"(p));
    return a;
}
__device__ __forceinline__ void ldm_x4(uint32_t addr, uint32_t* r) {
    asm volatile("ldmatrix.sync.aligned.m8n8.x4.shared.b16 {%0,%1,%2,%3}, [%4];"
        : "=r"(r[0]), "=r"(r[1]), "=r"(r[2]), "=r"(r[3]) : "r"(addr));
}
__device__ __forceinline__ void mma_tf32(float* d, const uint32_t* a, uint32_t b0, uint32_t b1) {
    asm volatile("mma.sync.aligned.m16n8k8.row.col.f32.tf32.tf32.f32 "
        "{%0,%1,%2,%3}, {%4,%5,%6,%7}, {%8,%9}, {%0,%1,%2,%3};"
        : "+f"(d[0]), "+f"(d[1]), "+f"(d[2]), "+f"(d[3])
        : "r"(a[0]), "r"(a[1]), "r"(a[2]), "r"(a[3]), "r"(b0), "r"(b1));
}
__device__ __forceinline__ void cp16(uint32_t dst, const void* src) {
    asm volatile("cp.async.cg.shared.global [%0], [%1], 16;" :: "r"(dst), "l"(src) : "memory");
}
#define CP_COMMIT() asm volatile("cp.async.commit_group;" ::: "memory")
#define CP_WAIT(n)  asm volatile("cp.async.wait_group %0;" :: "n"(n) : "memory")
__device__ __forceinline__ float sigmoidf_(float x) { return 1.0f / (1.0f + __expf(-x)); }
__device__ __forceinline__ float tf32r(float x) {
    float r;
    asm("cvt.rna.tf32.f32 %0, %1;" : "=f"(r) : "f"(x));
    return r;
}

// ---------------------------------------------------------------------------
// Prologue: transpose + tf32-round 6 weights into g_wf ([n][k])
// ---------------------------------------------------------------------------
__global__ void convert_w_kernel(const float* __restrict__ Wis, const float* __restrict__ Wi,
                                 const float* __restrict__ Wjs, const float* __restrict__ Wj,
                                 const float* __restrict__ Ws,  const float* __restrict__ Wp) {
    const float* src[6] = {Wis, Wi, Wjs, Wj, Ws, Wp};
    const float* W = src[blockIdx.x];
    float* outp = g_wf + (size_t)blockIdx.x * 16384;
    for (int idx = threadIdx.x; idx < 16384; idx += blockDim.x) {
        int n = idx >> 7, k = idx & 127;
        outp[n * 128 + k] = tf32r(W[k * 128 + n]);
    }
}

// cp.async one tf32 weight [128 n][132 f32 stride] into smem
__device__ __forceinline__ void loadWf512(int m, uint32_t sW, int tid) {
    const char* src = (const char*)g_wf + (size_t)m * 65536;
    #pragma unroll
    for (int it = 0; it < 8; ++it) {
        int idx = tid + it * 512;
        int row = idx >> 5, ch = idx & 31;
        cp16(sW + row * 528 + ch * 16, src + row * 512 + ch * 16);
    }
}

// ---------------------------------------------------------------------------
// tf32 warp GEMM: 32x32 warp tile, K=128, A/B row stride 528 B (132 f32)
// m16n8k8, fragments via ldmatrix.b16 (verified mapping).
// acc[(ma*4+na)*4+q]: q=0:(g,t2) 1:(g,t2+1) 2:(g+8,t2) 3:(g+8,t2+1)
// ---------------------------------------------------------------------------
__device__ __forceinline__ void wgemm_t32(uint32_t sA, uint32_t sB,
                                          int lane, int wm, int wn, float* acc) {
    int lr = lane & 7, sel = lane >> 3;
    uint32_t aRow = (uint32_t)((wm*32 + (sel & 1)*8 + lr) * 528 + (sel >> 1)*16);
    uint32_t bRow = (uint32_t)((wn*32 + (sel & 1)*8 + lr) * 528 + (sel >> 1)*16);
    #pragma unroll
    for (int kk = 0; kk < 16; ++kk) {          // k8 steps
        uint32_t a[2][4];
        #pragma unroll
        for (int ma = 0; ma < 2; ++ma)
            ldm_x4(sA + aRow + (uint32_t)(ma * 16 * 528 + kk * 32), a[ma]);
        #pragma unroll
        for (int p = 0; p < 2; ++p) {           // n16 groups
            uint32_t b[4];
            ldm_x4(sB + bRow + (uint32_t)(p * 16 * 528 + kk * 32), b);
            #pragma unroll
            for (int ma = 0; ma < 2; ++ma) {
                mma_tf32(acc + (ma*4 + p*2 + 0)*4, a[ma], b[0], b[2]);
                mma_tf32(acc + (ma*4 + p*2 + 1)*4, a[ma], b[1], b[3]);
            }
        }
    }
}

// dual: shared A fragments, two B matrices
__device__ __forceinline__ void wgemm_t32_dual(uint32_t sA, uint32_t sW0, uint32_t sW1,
                                               int lane, int wm, int wn,
                                               float* accg, float* accm) {
    int lr = lane & 7, sel = lane >> 3;
    uint32_t aRow = (uint32_t)((wm*32 + (sel & 1)*8 + lr) * 528 + (sel >> 1)*16);
    uint32_t bRow = (uint32_t)((wn*32 + (sel & 1)*8 + lr) * 528 + (sel >> 1)*16);
    #pragma unroll
    for (int kk = 0; kk < 16; ++kk) {
        uint32_t a[2][4];
        #pragma unroll
        for (int ma = 0; ma < 2; ++ma)
            ldm_x4(sA + aRow + (uint32_t)(ma * 16 * 528 + kk * 32), a[ma]);
        #pragma unroll
        for (int p = 0; p < 2; ++p) {
            uint32_t off = bRow + (uint32_t)(p * 16 * 528 + kk * 32);
            uint32_t b[4];
            ldm_x4(sW0 + off, b);
            #pragma unroll
            for (int ma = 0; ma < 2; ++ma) {
                mma_tf32(accg + (ma*4 + p*2 + 0)*4, a[ma], b[0], b[2]);
                mma_tf32(accg + (ma*4 + p*2 + 1)*4, a[ma], b[1], b[3]);
            }
            ldm_x4(sW1 + off, b);
            #pragma unroll
            for (int ma = 0; ma < 2; ++ma) {
                mma_tf32(accm + (ma*4 + p*2 + 0)*4, a[ma], b[0], b[2]);
                mma_tf32(accm + (ma*4 + p*2 + 1)*4, a[ma], b[1], b[3]);
            }
        }
    }
}

// ---------------------------------------------------------------------------
// Stage 1: LN(x) + 5 GEMMs (tf32, dual-fused), 512 threads, smem 202752 B
// smem: Xf | W0 | W1 (W1 doubles as f32 transpose staging)
// ---------------------------------------------------------------------------
__global__ void __launch_bounds__(512, 1)
stage1_kernel(const float* __restrict__ x2d, const float* __restrict__ mask,
              const float* __restrict__ ga1, const float* __restrict__ be1,
              const float* __restrict__ bi,  const float* __restrict__ bis,
              const float* __restrict__ bj,  const float* __restrict__ bjs,
              const float* __restrict__ bs) {
    float* Xf  = (float*)smem_;
    float* T1f = (float*)(smem_ + 2 * WFB);
    uint32_t sX  = smem_u32(Xf);
    uint32_t sW0 = sX + WFB;
    uint32_t sW1 = sX + 2 * WFB;

    int tid = threadIdx.x, lane = tid & 31, w = tid >> 5;
    int wm = w >> 2, wn = w & 3;
    int g = lane >> 2, t2 = (lane & 3) * 2;
    size_t rowbase = (size_t)blockIdx.x * 128;

    loadWf512(0, sW0, tid); CP_COMMIT();   // Wis
    loadWf512(1, sW1, tid); CP_COMMIT();   // Wi

    // layernorm: 4 threads/row, 32 channels each -> tf32-rounded Xf[r][k]
    {
        int r = tid >> 2, e = tid & 3;
        const float* xr = x2d + (rowbase + r) * C + e * 32;
        float v[32], s = 0.f, ss = 0.f;
        #pragma unroll
        for (int t = 0; t < 8; ++t) {
            float4 f = *(const float4*)(xr + t * 4);
            v[4*t+0]=f.x; v[4*t+1]=f.y; v[4*t+2]=f.z; v[4*t+3]=f.w;
            s += f.x + f.y + f.z + f.w;
            ss += f.x*f.x + f.y*f.y + f.z*f.z + f.w*f.w;
        }
        s  += __shfl_xor_sync(0xffffffffu, s, 1);
        s  += __shfl_xor_sync(0xffffffffu, s, 2);
        ss += __shfl_xor_sync(0xffffffffu, ss, 1);
        ss += __shfl_xor_sync(0xffffffffu, ss, 2);
        float mu = s * (1.0f / C);
        float rs = rsqrtf(ss * (1.0f / C) - mu * mu + 1e-5f);
        #pragma unroll
        for (int t = 0; t < 32; ++t) {
            int k = e * 32 + t;
            Xf[r * 132 + k] = tf32r((v[t] - mu) * rs * __ldg(ga1 + k) + __ldg(be1 + k));
        }
    }

    float accg[32], accm[32];

    #pragma unroll 1
    for (int pass = 0; pass < 2; ++pass) {
        const float* bgp = pass ? bjs : bis;
        const float* bmp = pass ? bj  : bi;
        float* outp = pass ? g_j : g_i;

        CP_WAIT(0);
        __syncthreads();
        #pragma unroll
        for (int q = 0; q < 32; ++q) { accg[q] = 0.f; accm[q] = 0.f; }
        wgemm_t32_dual(sX, sW0, sW1, lane, wm, wn, accg, accm);
        __syncthreads();                       // done reading W0/W1
        loadWf512(pass ? 4 : 2, sW0, tid);     // prefetch next gate / Ws
        CP_COMMIT();

        // combine -> staging T1f[col][row] (tf32-rounded)
        #pragma unroll
        for (int ma = 0; ma < 2; ++ma) {
            int r0 = wm*32 + ma*16 + g;
            float m0 = __ldg(mask + rowbase + r0);
            float m1 = __ldg(mask + rowbase + r0 + 8);
            #pragma unroll
            for (int na = 0; na < 4; ++na) {
                int idx = (ma*4 + na) * 4;
                int c0 = wn*32 + na*8 + t2;
                float bg0 = __ldg(bgp + c0), bg1 = __ldg(bgp + c0 + 1);
                float b0 = __ldg(bmp + c0),  b1 = __ldg(bmp + c0 + 1);
                T1f[(c0  )*132 + r0    ] = tf32r((accm[idx+0] + b0) * sigmoidf_(accg[idx+0] + bg0) * m0);
                T1f[(c0+1)*132 + r0    ] = tf32r((accm[idx+1] + b1) * sigmoidf_(accg[idx+1] + bg1) * m0);
                T1f[(c0  )*132 + r0 + 8] = tf32r((accm[idx+2] + b0) * sigmoidf_(accg[idx+2] + bg0) * m1);
                T1f[(c0+1)*132 + r0 + 8] = tf32r((accm[idx+3] + b1) * sigmoidf_(accg[idx+3] + bg1) * m1);
            }
        }
        __syncthreads();

        // channel-major flush (f32, coalesced)
        {
            int cch = tid >> 2, q = tid & 3;
            const float4* src = (const float4*)(T1f + cch * 132 + q * 32);
            float4* dst = (float4*)(outp + (size_t)cch * PLANE + rowbase + q * 32);
            #pragma unroll
            for (int t = 0; t < 8; ++t) dst[t] = src[t];
        }
        __syncthreads();
        if (pass == 0) { loadWf512(3, sW1, tid); CP_COMMIT(); }   // Wj
    }

    // sg = sigmoid(x@Ws+bs)
    CP_WAIT(0);
    __syncthreads();
    #pragma unroll
    for (int q = 0; q < 32; ++q) accg[q] = 0.f;
    wgemm_t32(sX, sW0, lane, wm, wn, accg);
    #pragma unroll
    for (int ma = 0; ma < 2; ++ma) {
        size_t r0 = rowbase + wm*32 + ma*16 + g;
        #pragma unroll
        for (int na = 0; na < 4; ++na) {
            int idx = (ma*4 + na) * 4;
            int c0 = wn*32 + na*8 + t2;
            float b0 = __ldg(bs + c0), b1 = __ldg(bs + c0 + 1);
            *(float2*)(g_sg + r0 * C + c0) =
                make_float2(sigmoidf_(accg[idx+0] + b0), sigmoidf_(accg[idx+1] + b1));
            *(float2*)(g_sg + (r0 + 8) * C + c0) =
                make_float2(sigmoidf_(accg[idx+2] + b0), sigmoidf_(accg[idx+3] + b1));
        }
    }
}

// ---------------------------------------------------------------------------
// Stage 2: einsum, tf32. block 128x256, 512 threads, 3 stages. (unchanged)
// ---------------------------------------------------------------------------
#define ESTG 55296

__device__ __forceinline__ void e_load(uint32_t sdst,
                                       const char* pA, const char* pB,
                                       int kb, int tid) {
    #pragma unroll
    for (int it = 0; it < 2; ++it) {
        int idx = tid + it * 512;
        int row = idx >> 3, ch = idx & 7;
        cp16(sdst + row * 144 + ch * 16,
             pA + (size_t)row * 2048 + kb * 128 + ch * 16);
    }
    #pragma unroll
    for (int it = 0; it < 4; ++it) {
        int idx = tid + it * 512;
        int row = idx >> 3, ch = idx & 7;
        cp16(sdst + 18432 + row * 144 + ch * 16,
             pB + (size_t)row * 2048 + kb * 128 + ch * 16);
    }
}

__device__ __forceinline__ void e_mma(uint32_t st, int lane, int wm, int wn, float* acc) {
    int lr = lane & 7, sel = lane >> 3;
    uint32_t aRow = (uint32_t)((wm*32 + (sel & 1)*8 + lr) * 144 + (sel >> 1)*16);
    uint32_t bRow = (uint32_t)((wn*64 + (sel & 1)*8 + lr) * 144 + (sel >> 1)*16);
    uint32_t sA = st, sB = st + 18432;
    #pragma unroll
    for (int kk = 0; kk < 4; ++kk) {
        uint32_t a[2][4];
        #pragma unroll
        for (int ma = 0; ma < 2; ++ma)
            ldm_x4(sA + aRow + (uint32_t)(ma * 16 * 144 + kk * 32), a[ma]);
        #pragma unroll
        for (int p = 0; p < 4; ++p) {
            uint32_t b[4];
            ldm_x4(sB + bRow + (uint32_t)(p * 16 * 144 + kk * 32), b);
            #pragma unroll
            for (int ma = 0; ma < 2; ++ma) {
                mma_tf32(acc + (ma*8 + p*2 + 0)*4, a[ma], b[0], b[2]);
                mma_tf32(acc + (ma*8 + p*2 + 1)*4, a[ma], b[1], b[3]);
            }
        }
    }
}

__global__ void __launch_bounds__(512, 1)
einsum_kernel() {
    uint32_t sb = smem_u32(smem_);
    int tid = threadIdx.x, lane = tid & 31, w = tid >> 5;
    int wm = w >> 2, wn = w & 3;
    int g = lane >> 2, t2 = (lane & 3) * 2;
    int c = blockIdx.z;
    int ibase = blockIdx.x * 128, jbase = blockIdx.y * 256;

    const char* pA = (const char*)(g_i + (size_t)c * PLANE + (size_t)ibase * NDIM);
    const char* pB = (const char*)(g_j + (size_t)c * PLANE + (size_t)jbase * NDIM);

    float acc[64];
    #pragma unroll
    for (int q = 0; q < 64; ++q) acc[q] = 0.f;

    e_load(sb,        pA, pB, 0, tid); CP_COMMIT();
    e_load(sb + ESTG, pA, pB, 1, tid); CP_COMMIT();

    #pragma unroll 1
    for (int kb = 0; kb < 16; ++kb) {
        if (kb < 15) { CP_WAIT(1); } else { CP_WAIT(0); }
        __syncthreads();
        if (kb + 2 < 16) {
            e_load(sb + ((kb + 2) % 3) * ESTG, pA, pB, kb + 2, tid);
            CP_COMMIT();
        }
        e_mma(sb + (kb % 3) * ESTG, lane, wm, wn, acc);
        __syncthreads();
    }

    float* O = g_ecm + (size_t)c * PLANE;
    #pragma unroll
    for (int ma = 0; ma < 2; ++ma) {
        size_t r0 = (size_t)(ibase + wm*32 + ma*16 + g);
        #pragma unroll
        for (int na = 0; na < 8; ++na) {
            int idx = (ma*8 + na) * 4;
            int c0 = jbase + wn*64 + na*8 + t2;
            *(float2*)(O + r0 * NDIM + c0)       = make_float2(acc[idx+0], acc[idx+1]);
            *(float2*)(O + (r0 + 8) * NDIM + c0) = make_float2(acc[idx+2], acc[idx+3]);
        }
    }
}

// ---------------------------------------------------------------------------
// Stage 3: 128-row blocks, 512 threads, tf32 GEMM.
// smem: Xf[128c][133] 68096 | XT[128r][132] 67584 | W 67584 = 203264 B
// ---------------------------------------------------------------------------
__global__ void __launch_bounds__(512, 1)
stage3_kernel(const float* __restrict__ mask,
              const float* __restrict__ ga2, const float* __restrict__ be2,
              const float* __restrict__ bp,  float* __restrict__ out) {
    float* Xf = (float*)smem_;                    // [128 c][133]
    float* XT = (float*)(smem_ + 68096);          // [128 r][132]
    uint32_t sXT = smem_u32(XT);
    uint32_t sW  = sXT + WFB;

    int tid = threadIdx.x, lane = tid & 31, w = tid >> 5;
    int wm = w >> 2, wn = w & 3;
    int g = lane >> 2, t2 = (lane & 3) * 2;
    size_t rowbase = (size_t)blockIdx.x * 128;

    loadWf512(5, sW, tid);
    CP_COMMIT();

    // coalesced gather: g_ecm[c][rowbase + r] -> Xf[c][r]
    #pragma unroll
    for (int it = 0; it < 32; ++it) {
        int idx = tid + it * 512;
        int c = idx >> 7, r = idx & 127;
        Xf[c * 133 + r] = __ldg(g_ecm + (size_t)c * PLANE + rowbase + r);
    }
    __syncthreads();

    // LN: warp per row, lane owns channels {lane, lane+32, lane+64, lane+96}
    #pragma unroll 1
    for (int it = 0; it < 8; ++it) {
        int r = w + it * 16;
        float v[4], s = 0.f, ss = 0.f;
        #pragma unroll
        for (int q = 0; q < 4; ++q) {
            float x = Xf[(lane + 32*q) * 133 + r];
            v[q] = x; s += x; ss += x * x;
        }
        #pragma unroll
        for (int d = 16; d >= 1; d >>= 1) {
            s  += __shfl_xor_sync(0xffffffffu, s, d);
            ss += __shfl_xor_sync(0xffffffffu, ss, d);
        }
        float mu = s * (1.0f / C);
        float rs = rsqrtf(ss * (1.0f / C) - mu * mu + 1e-5f);
        #pragma unroll
        for (int q = 0; q < 4; ++q) {
            int k = lane + 32*q;
            XT[r * 132 + k] = tf32r((v[q] - mu) * rs * __ldg(ga2 + k) + __ldg(be2 + k));
        }
    }
    CP_WAIT(0);
    __syncthreads();

    float acc[32];
    #pragma unroll
    for (int q = 0; q < 32; ++q) acc[q] = 0.f;
    wgemm_t32(sXT, sW, lane, wm, wn, acc);

    #pragma unroll
    for (int ma = 0; ma < 2; ++ma) {
        size_t r0 = rowbase + wm*32 + ma*16 + g;
        float m0 = __ldg(mask + r0);
        float m1 = __ldg(mask + r0 + 8);
        #pragma unroll
        for (int na = 0; na < 4; ++na) {
            int idx = (ma*4 + na) * 4;
            int c0 = wn*32 + na*8 + t2;
            float b0 = __ldg(bp + c0), b1 = __ldg(bp + c0 + 1);
            float2 s0 = *(const float2*)(g_sg + r0 * C + c0);
            float2 s1 = *(const float2*)(g_sg + (r0 + 8) * C + c0);
            *(float2*)(out + r0 * C + c0) =
                make_float2((acc[idx+0] + b0) * s0.x * m0, (acc[idx+1] + b1) * s0.y * m0);
            *(float2*)(out + (r0 + 8) * C + c0) =
                make_float2((acc[idx+2] + b0) * s1.x * m1, (acc[idx+3] + b1) * s1.y * m1);
        }
    }
}

// ---------------------------------------------------------------------------
extern "C" void kernel_launch(void* const* d_in, const int* in_sizes, int n_in,
                              void* d_out, int out_size) {
    const float* x2d  = (const float*)d_in[0];
    const float* mask = (const float*)d_in[1];
    const float* ga1  = (const float*)d_in[2];
    const float* be1  = (const float*)d_in[3];
    const float* ga2  = (const float*)d_in[4];
    const float* be2  = (const float*)d_in[5];
    const float* Wi   = (const float*)d_in[6];
    const float* bi   = (const float*)d_in[7];
    const float* Wis  = (const float*)d_in[8];
    const float* bis  = (const float*)d_in[9];
    const float* Wj   = (const float*)d_in[10];
    const float* bj   = (const float*)d_in[11];
    const float* Wjs  = (const float*)d_in[12];
    const float* bjs  = (const float*)d_in[13];
    const float* Wp   = (const float*)d_in[14];
    const float* bp   = (const float*)d_in[15];
    const float* Ws   = (const float*)d_in[16];
    const float* bs   = (const float*)d_in[17];

    const int smem_s1 = 3 * WFB;             // 202752
    const int smem_e  = 3 * ESTG;            // 165888
    const int smem_s3 = 68096 + 2 * WFB;     // 203264
    cudaFuncSetAttribute(stage1_kernel, cudaFuncAttributeMaxDynamicSharedMemorySize, smem_s1);
    cudaFuncSetAttribute(einsum_kernel, cudaFuncAttributeMaxDynamicSharedMemorySize, smem_e);
    cudaFuncSetAttribute(stage3_kernel, cudaFuncAttributeMaxDynamicSharedMemorySize, smem_s3);

    convert_w_kernel<<<6, 256>>>(Wis, Wi, Wjs, Wj, Ws, Wp);

    stage1_kernel<<<NN / 128, 512, smem_s1>>>(x2d, mask, ga1, be1,
                                              bi, bis, bj, bjs, bs);

    dim3 grid2(NDIM / 128, NDIM / 256, C);
    einsum_kernel<<<grid2, 512, smem_e>>>();

    stage3_kernel<<<NN / 128, 512, smem_s3>>>(mask, ga2, be2, bp, (float*)d_out);
}

// round 10
// speedup vs baseline: 1.1534x; 1.0664x over previous
#include <cuda_runtime.h>
#include <cuda_bf16.h>
#include <cstdint>
#include <math.h>

#define NDIM 512
#define C 128
#define NN (NDIM*NDIM)
#define PLANE NN
#define WFB 67584          // 128 x 132 f32 weight array bytes
#define XFB 33792          // 64 x 132 f32 activation array bytes

// ---------------------------------------------------------------------------
// scratch
// ---------------------------------------------------------------------------
__device__ __align__(16) float g_i[(size_t)C*NN];     // tf32-rounded, channel-major
__device__ __align__(16) float g_j[(size_t)C*NN];
__device__ __align__(16) float g_ecm[(size_t)C*NN];
__device__ __align__(16) float g_sg [(size_t)NN*C];
__device__ __align__(16) float g_wf[6 * 128 * 128];   // tf32 [n][k]: Wis Wi Wjs Wj Ws Wp

extern __shared__ char smem_[];

// ---------------------------------------------------------------------------
// PTX helpers
// ---------------------------------------------------------------------------
__device__ __forceinline__ uint32_t smem_u32(const void* p) {
    uint32_t a;
    asm("{ .reg .u64 t; cvta.to.shared.u64 t, %1; cvt.u32.u64 %0, t; }" : "=r"(a) : "l"(p));
    return a;
}
__device__ __forceinline__ void ldm_x4(uint32_t addr, uint32_t* r) {
    asm volatile("ldmatrix.sync.aligned.m8n8.x4.shared.b16 {%0,%1,%2,%3}, [%4];"
        : "=r"(r[0]), "=r"(r[1]), "=r"(r[2]), "=r"(r[3]) : "r"(addr));
}
__device__ __forceinline__ void mma_tf32(float* d, const uint32_t* a, uint32_t b0, uint32_t b1) {
    asm volatile("mma.sync.aligned.m16n8k8.row.col.f32.tf32.tf32.f32 "
        "{%0,%1,%2,%3}, {%4,%5,%6,%7}, {%8,%9}, {%0,%1,%2,%3};"
        : "+f"(d[0]), "+f"(d[1]), "+f"(d[2]), "+f"(d[3])
        : "r"(a[0]), "r"(a[1]), "r"(a[2]), "r"(a[3]), "r"(b0), "r"(b1));
}
__device__ __forceinline__ void cp16(uint32_t dst, const void* src) {
    asm volatile("cp.async.cg.shared.global [%0], [%1], 16;" :: "r"(dst), "l"(src) : "memory");
}
#define CP_COMMIT() asm volatile("cp.async.commit_group;" ::: "memory")
#define CP_WAIT(n)  asm volatile("cp.async.wait_group %0;" :: "n"(n) : "memory")
__device__ __forceinline__ float sigmoidf_(float x) { return 1.0f / (1.0f + __expf(-x)); }
__device__ __forceinline__ float tf32r(float x) {
    float r;
    asm("cvt.rna.tf32.f32 %0, %1;" : "=f"(r) : "f"(x));
    return r;
}

// ---------------------------------------------------------------------------
// Prologue: transpose + tf32-round weights
// ---------------------------------------------------------------------------
__global__ void convert_w_kernel(const float* __restrict__ Wis, const float* __restrict__ Wi,
                                 const float* __restrict__ Wjs, const float* __restrict__ Wj,
                                 const float* __restrict__ Ws,  const float* __restrict__ Wp) {
    const float* src[6] = {Wis, Wi, Wjs, Wj, Ws, Wp};
    const float* W = src[blockIdx.x];
    float* outp = g_wf + (size_t)blockIdx.x * 16384;
    for (int idx = threadIdx.x; idx < 16384; idx += blockDim.x) {
        int n = idx >> 7, k = idx & 127;
        outp[n * 128 + k] = tf32r(W[k * 128 + n]);
    }
}

// cp.async one tf32 weight [128 n][132 f32 stride] into smem, 256 threads
__device__ __forceinline__ void loadWf(int m, uint32_t sW, int tid) {
    const char* src = (const char*)g_wf + (size_t)m * 65536;
    #pragma unroll
    for (int it = 0; it < 16; ++it) {
        int idx = tid + it * 256;
        int row = idx >> 5, ch = idx & 31;
        cp16(sW + row * 528 + ch * 16, src + row * 512 + ch * 16);
    }
}

// ---------------------------------------------------------------------------
// tf32 warp GEMM: 32x32 warp tile, K=128, row stride 528 B
// 8 warps: wm=w>>2 (2, rows), wn=w&3 (4, cols) -> 64x128 block tile
// acc[(ma*4+na)*4+q]: q=0:(g,t2) 1:(g,t2+1) 2:(g+8,t2) 3:(g+8,t2+1)
// ---------------------------------------------------------------------------
__device__ __forceinline__ void wgemm_t32(uint32_t sA, uint32_t sB,
                                          int lane, int wm, int wn, float* acc) {
    int lr = lane & 7, sel = lane >> 3;
    uint32_t aRow = (uint32_t)((wm*32 + (sel & 1)*8 + lr) * 528 + (sel >> 1)*16);
    uint32_t bRow = (uint32_t)((wn*32 + (sel & 1)*8 + lr) * 528 + (sel >> 1)*16);
    #pragma unroll
    for (int kk = 0; kk < 16; ++kk) {
        uint32_t a[2][4];
        #pragma unroll
        for (int ma = 0; ma < 2; ++ma)
            ldm_x4(sA + aRow + (uint32_t)(ma * 16 * 528 + kk * 32), a[ma]);
        #pragma unroll
        for (int p = 0; p < 2; ++p) {
            uint32_t b[4];
            ldm_x4(sB + bRow + (uint32_t)(p * 16 * 528 + kk * 32), b);
            #pragma unroll
            for (int ma = 0; ma < 2; ++ma) {
                mma_tf32(acc + (ma*4 + p*2 + 0)*4, a[ma], b[0], b[2]);
                mma_tf32(acc + (ma*4 + p*2 + 1)*4, a[ma], b[1], b[3]);
            }
        }
    }
}

// ---------------------------------------------------------------------------
// Stage 1: LN + 5 GEMMs. 256 threads, 64-row tiles, 2 CTAs/SM.
// smem: Xf 64x132 f32 (33792) | W 128x132 f32 (67584) = 101376 B
// ---------------------------------------------------------------------------
__global__ void __launch_bounds__(256, 2)
stage1_kernel(const float* __restrict__ x2d, const float* __restrict__ mask,
              const float* __restrict__ ga1, const float* __restrict__ be1,
              const float* __restrict__ bi,  const float* __restrict__ bis,
              const float* __restrict__ bj,  const float* __restrict__ bjs,
              const float* __restrict__ bs) {
    float* Xf = (float*)smem_;
    float* T  = (float*)(smem_ + XFB);     // W region; doubles as staging
    uint32_t sX = smem_u32(Xf);
    uint32_t sW = sX + XFB;

    int tid = threadIdx.x, lane = tid & 31, w = tid >> 5;
    int wm = w >> 2, wn = w & 3;
    int g = lane >> 2, t2 = (lane & 3) * 2;
    size_t rowbase = (size_t)blockIdx.x * 64;

    loadWf(0, sW, tid); CP_COMMIT();   // Wis

    // layernorm: 4 threads/row, 32 channels each
    {
        int r = tid >> 2, e = tid & 3;
        const float* xr = x2d + (rowbase + r) * C + e * 32;
        float v[32], s = 0.f, ss = 0.f;
        #pragma unroll
        for (int t = 0; t < 8; ++t) {
            float4 f = *(const float4*)(xr + t * 4);
            v[4*t+0]=f.x; v[4*t+1]=f.y; v[4*t+2]=f.z; v[4*t+3]=f.w;
            s += f.x + f.y + f.z + f.w;
            ss += f.x*f.x + f.y*f.y + f.z*f.z + f.w*f.w;
        }
        s  += __shfl_xor_sync(0xffffffffu, s, 1);
        s  += __shfl_xor_sync(0xffffffffu, s, 2);
        ss += __shfl_xor_sync(0xffffffffu, ss, 1);
        ss += __shfl_xor_sync(0xffffffffu, ss, 2);
        float mu = s * (1.0f / C);
        float rs = rsqrtf(ss * (1.0f / C) - mu * mu + 1e-5f);
        #pragma unroll
        for (int t = 0; t < 32; ++t) {
            int k = e * 32 + t;
            Xf[r * 132 + k] = tf32r((v[t] - mu) * rs * __ldg(ga1 + k) + __ldg(be1 + k));
        }
    }

    float accg[32], accm[32];

    #pragma unroll 1
    for (int pass = 0; pass < 2; ++pass) {
        const float* bgp = pass ? bjs : bis;
        const float* bmp = pass ? bj  : bi;
        float* outp = pass ? g_j : g_i;

        // gate GEMM
        CP_WAIT(0);
        __syncthreads();
        #pragma unroll
        for (int q = 0; q < 32; ++q) accg[q] = 0.f;
        wgemm_t32(sX, sW, lane, wm, wn, accg);
        #pragma unroll
        for (int ma = 0; ma < 2; ++ma)
            #pragma unroll
            for (int na = 0; na < 4; ++na) {
                int idx = (ma*4 + na) * 4;
                int c0 = wn*32 + na*8 + t2;
                float b0 = __ldg(bgp + c0), b1 = __ldg(bgp + c0 + 1);
                accg[idx+0] = sigmoidf_(accg[idx+0] + b0);
                accg[idx+1] = sigmoidf_(accg[idx+1] + b1);
                accg[idx+2] = sigmoidf_(accg[idx+2] + b0);
                accg[idx+3] = sigmoidf_(accg[idx+3] + b1);
            }
        __syncthreads();                        // done reading W
        loadWf(2*pass + 1, sW, tid); CP_COMMIT();   // main weight

        // main GEMM
        CP_WAIT(0);
        __syncthreads();
        #pragma unroll
        for (int q = 0; q < 32; ++q) accm[q] = 0.f;
        wgemm_t32(sX, sW, lane, wm, wn, accm);
        __syncthreads();                        // done reading W -> staging

        // combine -> T[col][row] (stride 68)
        #pragma unroll
        for (int ma = 0; ma < 2; ++ma) {
            int r0 = wm*32 + ma*16 + g;
            float m0 = __ldg(mask + rowbase + r0);
            float m1 = __ldg(mask + rowbase + r0 + 8);
            #pragma unroll
            for (int na = 0; na < 4; ++na) {
                int idx = (ma*4 + na) * 4;
                int c0 = wn*32 + na*8 + t2;
                float b0 = __ldg(bmp + c0), b1 = __ldg(bmp + c0 + 1);
                T[(c0  )*68 + r0    ] = tf32r((accm[idx+0] + b0) * accg[idx+0] * m0);
                T[(c0+1)*68 + r0    ] = tf32r((accm[idx+1] + b1) * accg[idx+1] * m0);
                T[(c0  )*68 + r0 + 8] = tf32r((accm[idx+2] + b0) * accg[idx+2] * m1);
                T[(c0+1)*68 + r0 + 8] = tf32r((accm[idx+3] + b1) * accg[idx+3] * m1);
            }
        }
        __syncthreads();

        // channel-major flush
        {
            int cch = tid >> 1, q = tid & 1;
            const float4* src = (const float4*)(T + cch * 68 + q * 32);
            float4* dst = (float4*)(outp + (size_t)cch * PLANE + rowbase + q * 32);
            #pragma unroll
            for (int t = 0; t < 8; ++t) dst[t] = src[t];
        }
        __syncthreads();
        loadWf(pass == 0 ? 2 : 4, sW, tid); CP_COMMIT();   // next gate / Ws
    }

    // sg = sigmoid(x@Ws+bs)
    CP_WAIT(0);
    __syncthreads();
    #pragma unroll
    for (int q = 0; q < 32; ++q) accg[q] = 0.f;
    wgemm_t32(sX, sW, lane, wm, wn, accg);
    #pragma unroll
    for (int ma = 0; ma < 2; ++ma) {
        size_t r0 = rowbase + wm*32 + ma*16 + g;
        #pragma unroll
        for (int na = 0; na < 4; ++na) {
            int idx = (ma*4 + na) * 4;
            int c0 = wn*32 + na*8 + t2;
            float b0 = __ldg(bs + c0), b1 = __ldg(bs + c0 + 1);
            *(float2*)(g_sg + r0 * C + c0) =
                make_float2(sigmoidf_(accg[idx+0] + b0), sigmoidf_(accg[idx+1] + b1));
            *(float2*)(g_sg + (r0 + 8) * C + c0) =
                make_float2(sigmoidf_(accg[idx+2] + b0), sigmoidf_(accg[idx+3] + b1));
        }
    }
}

// ---------------------------------------------------------------------------
// Stage 2: einsum, tf32, block 128x128, 256 threads, 2 CTAs/SM.
// stage: A 128x36 f32 (144 B rows) 18432 + B 18432 = 36864; 2 stages = 73728 B
// warp tile 32x64: wm=w>>1 (4, rows), wn=w&1 (2, cols)
// ---------------------------------------------------------------------------
#define ESTG 36864

__device__ __forceinline__ void e_load(uint32_t sdst,
                                       const char* pA, const char* pB,
                                       int kb, int tid) {
    #pragma unroll
    for (int it = 0; it < 4; ++it) {
        int idx = tid + it * 256;
        int row = idx >> 3, ch = idx & 7;
        cp16(sdst + row * 144 + ch * 16,
             pA + (size_t)row * 2048 + kb * 128 + ch * 16);
    }
    #pragma unroll
    for (int it = 0; it < 4; ++it) {
        int idx = tid + it * 256;
        int row = idx >> 3, ch = idx & 7;
        cp16(sdst + 18432 + row * 144 + ch * 16,
             pB + (size_t)row * 2048 + kb * 128 + ch * 16);
    }
}

__device__ __forceinline__ void e_mma(uint32_t st, int lane, int wm, int wn, float* acc) {
    int lr = lane & 7, sel = lane >> 3;
    uint32_t aRow = (uint32_t)((wm*32 + (sel & 1)*8 + lr) * 144 + (sel >> 1)*16);
    uint32_t bRow = (uint32_t)((wn*64 + (sel & 1)*8 + lr) * 144 + (sel >> 1)*16);
    uint32_t sA = st, sB = st + 18432;
    #pragma unroll
    for (int kk = 0; kk < 4; ++kk) {
        uint32_t a[2][4];
        #pragma unroll
        for (int ma = 0; ma < 2; ++ma)
            ldm_x4(sA + aRow + (uint32_t)(ma * 16 * 144 + kk * 32), a[ma]);
        #pragma unroll
        for (int p = 0; p < 4; ++p) {
            uint32_t b[4];
            ldm_x4(sB + bRow + (uint32_t)(p * 16 * 144 + kk * 32), b);
            #pragma unroll
            for (int ma = 0; ma < 2; ++ma) {
                mma_tf32(acc + (ma*8 + p*2 + 0)*4, a[ma], b[0], b[2]);
                mma_tf32(acc + (ma*8 + p*2 + 1)*4, a[ma], b[1], b[3]);
            }
        }
    }
}

__global__ void __launch_bounds__(256, 2)
einsum_kernel() {
    uint32_t sb = smem_u32(smem_);
    int tid = threadIdx.x, lane = tid & 31, w = tid >> 5;
    int wm = w >> 1, wn = w & 1;
    int g = lane >> 2, t2 = (lane & 3) * 2;
    int c = blockIdx.z;
    int ibase = blockIdx.x * 128, jbase = blockIdx.y * 128;

    const char* pA = (const char*)(g_i + (size_t)c * PLANE + (size_t)ibase * NDIM);
    const char* pB = (const char*)(g_j + (size_t)c * PLANE + (size_t)jbase * NDIM);

    float acc[64];
    #pragma unroll
    for (int q = 0; q < 64; ++q) acc[q] = 0.f;

    e_load(sb, pA, pB, 0, tid); CP_COMMIT();

    #pragma unroll 1
    for (int kb = 0; kb < 16; ++kb) {
        if (kb < 15) {
            e_load(sb + ((kb + 1) & 1) * ESTG, pA, pB, kb + 1, tid);
            CP_COMMIT();
            CP_WAIT(1);
        } else {
            CP_WAIT(0);
        }
        __syncthreads();
        e_mma(sb + (kb & 1) * ESTG, lane, wm, wn, acc);
        __syncthreads();
    }

    float* O = g_ecm + (size_t)c * PLANE;
    #pragma unroll
    for (int ma = 0; ma < 2; ++ma) {
        size_t r0 = (size_t)(ibase + wm*32 + ma*16 + g);
        #pragma unroll
        for (int na = 0; na < 8; ++na) {
            int idx = (ma*8 + na) * 4;
            int c0 = jbase + wn*64 + na*8 + t2;
            *(float2*)(O + r0 * NDIM + c0)       = make_float2(acc[idx+0], acc[idx+1]);
            *(float2*)(O + (r0 + 8) * NDIM + c0) = make_float2(acc[idx+2], acc[idx+3]);
        }
    }
}

// ---------------------------------------------------------------------------
// Stage 3: 64-row tiles, 256 threads, 2 CTAs/SM.
// smem: XT 64x132 f32 (33792) | W (67584) = 101376 B
// ---------------------------------------------------------------------------
__global__ void __launch_bounds__(256, 2)
stage3_kernel(const float* __restrict__ mask,
              const float* __restrict__ ga2, const float* __restrict__ be2,
              const float* __restrict__ bp,  float* __restrict__ out) {
    float* XT = (float*)smem_;
    uint32_t sXT = smem_u32(XT);
    uint32_t sW  = sXT + XFB;

    int tid = threadIdx.x, lane = tid & 31, w = tid >> 5;
    int wm = w >> 2, wn = w & 3;
    int g = lane >> 2, t2 = (lane & 3) * 2;
    size_t rowbase = (size_t)blockIdx.x * 64;

    loadWf(5, sW, tid);
    CP_COMMIT();

    // gather channel-major einsum output + LN over channels
    {
        int r = tid >> 2, e = tid & 3;
        const float* base = g_ecm + (size_t)(e * 32) * PLANE + rowbase + r;
        float v[32], s = 0.f, ss = 0.f;
        #pragma unroll
        for (int t = 0; t < 32; ++t) {
            float x = __ldg(base + (size_t)t * PLANE);
            v[t] = x; s += x; ss += x * x;
        }
        s  += __shfl_xor_sync(0xffffffffu, s, 1);
        s  += __shfl_xor_sync(0xffffffffu, s, 2);
        ss += __shfl_xor_sync(0xffffffffu, ss, 1);
        ss += __shfl_xor_sync(0xffffffffu, ss, 2);
        float mu = s * (1.0f / C);
        float rs = rsqrtf(ss * (1.0f / C) - mu * mu + 1e-5f);
        #pragma unroll
        for (int t = 0; t < 32; ++t) {
            int k = e * 32 + t;
            XT[r * 132 + k] = tf32r((v[t] - mu) * rs * __ldg(ga2 + k) + __ldg(be2 + k));
        }
    }
    CP_WAIT(0);
    __syncthreads();

    float acc[32];
    #pragma unroll
    for (int q = 0; q < 32; ++q) acc[q] = 0.f;
    wgemm_t32(sXT, sW, lane, wm, wn, acc);

    #pragma unroll
    for (int ma = 0; ma < 2; ++ma) {
        size_t r0 = rowbase + wm*32 + ma*16 + g;
        float m0 = __ldg(mask + r0);
        float m1 = __ldg(mask + r0 + 8);
        #pragma unroll
        for (int na = 0; na < 4; ++na) {
            int idx = (ma*4 + na) * 4;
            int c0 = wn*32 + na*8 + t2;
            float b0 = __ldg(bp + c0), b1 = __ldg(bp + c0 + 1);
            float2 s0 = *(const float2*)(g_sg + r0 * C + c0);
            float2 s1 = *(const float2*)(g_sg + (r0 + 8) * C + c0);
            *(float2*)(out + r0 * C + c0) =
                make_float2((acc[idx+0] + b0) * s0.x * m0, (acc[idx+1] + b1) * s0.y * m0);
            *(float2*)(out + (r0 + 8) * C + c0) =
                make_float2((acc[idx+2] + b0) * s1.x * m1, (acc[idx+3] + b1) * s1.y * m1);
        }
    }
}

// ---------------------------------------------------------------------------
extern "C" void kernel_launch(void* const* d_in, const int* in_sizes, int n_in,
                              void* d_out, int out_size) {
    const float* x2d  = (const float*)d_in[0];
    const float* mask = (const float*)d_in[1];
    const float* ga1  = (const float*)d_in[2];
    const float* be1  = (const float*)d_in[3];
    const float* ga2  = (const float*)d_in[4];
    const float* be2  = (const float*)d_in[5];
    const float* Wi   = (const float*)d_in[6];
    const float* bi   = (const float*)d_in[7];
    const float* Wis  = (const float*)d_in[8];
    const float* bis  = (const float*)d_in[9];
    const float* Wj   = (const float*)d_in[10];
    const float* bj   = (const float*)d_in[11];
    const float* Wjs  = (const float*)d_in[12];
    const float* bjs  = (const float*)d_in[13];
    const float* Wp   = (const float*)d_in[14];
    const float* bp   = (const float*)d_in[15];
    const float* Ws   = (const float*)d_in[16];
    const float* bs   = (const float*)d_in[17];

    const int smem_s1 = XFB + WFB;     // 101376
    const int smem_e  = 2 * ESTG;      // 73728
    const int smem_s3 = XFB + WFB;     // 101376
    cudaFuncSetAttribute(stage1_kernel, cudaFuncAttributeMaxDynamicSharedMemorySize, smem_s1);
    cudaFuncSetAttribute(einsum_kernel, cudaFuncAttributeMaxDynamicSharedMemorySize, smem_e);
    cudaFuncSetAttribute(stage3_kernel, cudaFuncAttributeMaxDynamicSharedMemorySize, smem_s3);

    convert_w_kernel<<<6, 256>>>(Wis, Wi, Wjs, Wj, Ws, Wp);

    stage1_kernel<<<NN / 64, 256, smem_s1>>>(x2d, mask, ga1, be1,
                                             bi, bis, bj, bjs, bs);

    dim3 grid2(NDIM / 128, NDIM / 128, C);
    einsum_kernel<<<grid2, 256, smem_e>>>();

    stage3_kernel<<<NN / 64, 256, smem_s3>>>(mask, ga2, be2, bp, (float*)d_out);
}